// round 7
// baseline (speedup 1.0000x reference)
#include <cuda_runtime.h>
#include <cstdint>

#define B_ 4
#define N_ 4096
#define C_ 1024
#define H_ 16
#define D_ 64
#define M1 (B_*N_)      // 16384 rows
#define N1 (3*C_)       // 3072 qkv cols
#define SPLITS 16
#define CHUNK (N_/SPLITS) // 256 rows per split

// ---- scratch (no allocs allowed; __device__ globals) ----
__device__ float g_qkv [(size_t)M1 * N1];          // 201 MB
__device__ float g_attn[(size_t)M1 * C_];          //  64 MB
__device__ float g_kvp [64 * SPLITS * 64 * 64];
__device__ float g_ksump[64 * SPLITS * 64];
__device__ float g_kv  [64 * 64 * 64];
__device__ float g_ksum[64 * 64];

// ============================================================
// tf32 / cp.async helpers
// ============================================================
__device__ __forceinline__ uint32_t f2tf32u(float x) {
    uint32_t r;
    asm("cvt.rna.tf32.f32 %0, %1;" : "=r"(r) : "f"(x));
    return r;
}

__device__ __forceinline__ void mma_tf32(float* c, const uint32_t* a, const uint32_t* b) {
    asm volatile(
        "mma.sync.aligned.m16n8k8.row.col.f32.tf32.tf32.f32 "
        "{%0,%1,%2,%3}, {%4,%5,%6,%7}, {%8,%9}, {%0,%1,%2,%3};"
        : "+f"(c[0]), "+f"(c[1]), "+f"(c[2]), "+f"(c[3])
        : "r"(a[0]), "r"(a[1]), "r"(a[2]), "r"(a[3]), "r"(b[0]), "r"(b[1]));
}

__device__ __forceinline__ void cp16(float* smem_dst, const float* gmem_src) {
    asm volatile("cp.async.cg.shared.global [%0], [%1], 16;\n"
        :: "r"((uint32_t)__cvta_generic_to_shared(smem_dst)), "l"(gmem_src));
}
#define CP_COMMIT() asm volatile("cp.async.commit_group;\n" ::)
#define CP_WAIT(n)  asm volatile("cp.async.wait_group %0;\n" :: "n"(n))

// ============================================================
// tf32 tensor-core GEMM: C[M,N] = A[M,K] @ B[K,N], fp32 in/out.
// 256x128 CTA tile, BK=16, 3-stage cp.async pipeline, 256 thr
// (8 warps, 4x2), warp tile 64x64 (4x8 of m16n8k8).
// Raw fp32 in smem; cvt.rna.tf32 applied to fragments (same
// numerics as converting before store). Conflict-free banking.
// MODE 1: elu(x)+1 on cols < 2048.  MODE 2: += bias[col].
// Requires M%256==0, N%128==0, K%16==0.
// ============================================================
#define BKG 16
#define ASTR 20                    // A row pitch (floats), conflict-free
#define BSTR 136                   // B row pitch (floats), conflict-free
#define A_FLOATS (256 * ASTR)      // 5120
#define B_FLOATS (BKG * BSTR)      // 2176
#define STG_FLOATS (A_FLOATS + B_FLOATS)   // 7296
#define NSTAGES 3
#define GEMM_SMEM (NSTAGES * STG_FLOATS * 4)  // 87552 bytes

template<int MODE>
__global__ __launch_bounds__(256, 1) void tf32gemm(
    const float* __restrict__ A, const float* __restrict__ Bm,
    float* __restrict__ C, int M, int N, int K,
    const float* __restrict__ bias)
{
    extern __shared__ float sm[];

    const int tid  = threadIdx.x;
    const int lane = tid & 31;
    const int warp = tid >> 5;
    const int wr = warp >> 1;            // 0..3  (64-row slabs)
    const int wc = warp & 1;             // 0..1  (64-col slabs)
    const int bx = blockIdx.x, by = blockIdx.y;
    const int la3 = lane & 3;
    const int l4  = lane >> 2;

    const float* Abase = A + (size_t)(by * 256) * K;
    const float* Bbase = Bm + (size_t)bx * 128;

    // issue cp.async for one k-tile into stage s
    #define LOAD_STAGE(s, kk)                                                  \
        do {                                                                   \
            float* as_ = sm + (s) * STG_FLOATS;                                \
            float* bs_ = as_ + A_FLOATS;                                       \
            _Pragma("unroll")                                                  \
            for (int i = 0; i < 4; i++) {                                      \
                int idx = tid + 256 * i;                                       \
                int r = idx >> 2, c4 = (idx & 3) * 4;                          \
                cp16(as_ + r * ASTR + c4, Abase + (size_t)r * K + (kk) + c4);  \
            }                                                                  \
            _Pragma("unroll")                                                  \
            for (int i = 0; i < 2; i++) {                                      \
                int idx = tid + 256 * i;                                       \
                int r = idx >> 5, c4 = (idx & 31) * 4;                         \
                cp16(bs_ + r * BSTR + c4, Bbase + (size_t)((kk) + r) * N + c4);\
            }                                                                  \
            CP_COMMIT();                                                       \
        } while (0)

    const int nT = K / BKG;
    LOAD_STAGE(0, 0);
    LOAD_STAGE(1, BKG);

    float acc[4][8][4] = {};

    for (int t = 0; t < nT; t++) {
        if (t + 1 < nT) { CP_WAIT(1); } else { CP_WAIT(0); }
        __syncthreads();

        // prefetch t+2 into the stage freed by compute(t-1)
        if (t + 2 < nT) {
            int s2 = (t + 2) % NSTAGES;
            LOAD_STAGE(s2, (t + 2) * BKG);
        }

        const float* as_ = sm + (t % NSTAGES) * STG_FLOATS;
        const float* bs_ = as_ + A_FLOATS;

        #pragma unroll
        for (int ks = 0; ks < BKG; ks += 8) {
            uint32_t af[4][4], bf[8][2];
            #pragma unroll
            for (int mt = 0; mt < 4; mt++) {
                int rb = wr * 64 + mt * 16 + l4;
                af[mt][0] = f2tf32u(as_[(rb    ) * ASTR + ks     + la3]);
                af[mt][1] = f2tf32u(as_[(rb + 8) * ASTR + ks     + la3]);
                af[mt][2] = f2tf32u(as_[(rb    ) * ASTR + ks + 4 + la3]);
                af[mt][3] = f2tf32u(as_[(rb + 8) * ASTR + ks + 4 + la3]);
            }
            #pragma unroll
            for (int nt = 0; nt < 8; nt++) {
                int nb = wc * 64 + nt * 8 + l4;
                bf[nt][0] = f2tf32u(bs_[(ks     + la3) * BSTR + nb]);
                bf[nt][1] = f2tf32u(bs_[(ks + 4 + la3) * BSTR + nb]);
            }
            #pragma unroll
            for (int mt = 0; mt < 4; mt++)
                #pragma unroll
                for (int nt = 0; nt < 8; nt++)
                    mma_tf32(acc[mt][nt], af[mt], bf[nt]);
        }
    }

    // epilogue
    #pragma unroll
    for (int mt = 0; mt < 4; mt++) {
        #pragma unroll
        for (int nt = 0; nt < 8; nt++) {
            int row = by * 256 + wr * 64 + mt * 16 + l4;
            int col = bx * 128 + wc * 64 + nt * 8 + la3 * 2;
            float v0 = acc[mt][nt][0], v1 = acc[mt][nt][1];
            float v2 = acc[mt][nt][2], v3 = acc[mt][nt][3];
            if (MODE == 1) {
                if (col < 2 * C_) {   // q,k columns: elu(x)+1
                    v0 = (v0 > 0.f) ? (v0 + 1.f) : __expf(v0);
                    v1 = (v1 > 0.f) ? (v1 + 1.f) : __expf(v1);
                    v2 = (v2 > 0.f) ? (v2 + 1.f) : __expf(v2);
                    v3 = (v3 > 0.f) ? (v3 + 1.f) : __expf(v3);
                }
            } else if (MODE == 2) {
                float b0 = bias[col], b1 = bias[col + 1];
                v0 += b0; v1 += b1; v2 += b0; v3 += b1;
            }
            *reinterpret_cast<float2*>(C + (size_t)row * N + col)       = make_float2(v0, v1);
            *reinterpret_cast<float2*>(C + (size_t)(row + 8) * N + col) = make_float2(v2, v3);
        }
    }
}

// ============================================================
// Phase 2: per (b,h) split-K partials of kv[d][e] = sum_n k*v
// and ksum[d] = sum_n k.  Deterministic (no atomics).
// ============================================================
__global__ __launch_bounds__(256) void kv_partial_kernel(const float* __restrict__ qkv)
{
    int bh = blockIdx.x;
    int b = bh >> 4, h = bh & 15;
    int n0 = blockIdx.y * CHUNK;
    int tid = threadIdx.x;
    int d0 = (tid >> 4) * 4, e0 = (tid & 15) * 4;

    __shared__ float ks[32][64];
    __shared__ float vs[32][64];

    float acc[4][4] = {};
    float ksacc[4] = {0.f, 0.f, 0.f, 0.f};

    const float* base = qkv + (size_t)b * N_ * N1 + h * 64;

    for (int nt = 0; nt < CHUNK; nt += 32) {
        for (int l = tid; l < 512; l += 256) {
            int r = l >> 4; int c = (l & 15) * 4;
            size_t off = (size_t)(n0 + nt + r) * N1 + c;
            *reinterpret_cast<float4*>(&ks[r][c]) =
                *reinterpret_cast<const float4*>(base + 1024 + off);
            *reinterpret_cast<float4*>(&vs[r][c]) =
                *reinterpret_cast<const float4*>(base + 2048 + off);
        }
        __syncthreads();
        #pragma unroll 4
        for (int r = 0; r < 32; r++) {
            float kr[4], vr[4];
            *reinterpret_cast<float4*>(kr) = *reinterpret_cast<float4*>(&ks[r][d0]);
            *reinterpret_cast<float4*>(vr) = *reinterpret_cast<float4*>(&vs[r][e0]);
            #pragma unroll
            for (int i = 0; i < 4; i++)
                #pragma unroll
                for (int j = 0; j < 4; j++)
                    acc[i][j] += kr[i] * vr[j];
            if (e0 == 0) {
                #pragma unroll
                for (int i = 0; i < 4; i++) ksacc[i] += kr[i];
            }
        }
        __syncthreads();
    }

    float* kvp = g_kvp + (size_t)(bh * SPLITS + blockIdx.y) * 4096;
    #pragma unroll
    for (int i = 0; i < 4; i++)
        #pragma unroll
        for (int j = 0; j < 4; j++)
            kvp[(d0 + i) * 64 + e0 + j] = acc[i][j];
    if (e0 == 0) {
        float* ksp = g_ksump + (size_t)(bh * SPLITS + blockIdx.y) * 64;
        #pragma unroll
        for (int i = 0; i < 4; i++) ksp[d0 + i] = ksacc[i];
    }
}

__global__ __launch_bounds__(256) void kv_reduce_kernel()
{
    int bh = blockIdx.x; int tid = threadIdx.x;
    for (int idx = tid; idx < 4096; idx += 256) {
        float s = 0.f;
        #pragma unroll
        for (int p = 0; p < SPLITS; p++)
            s += g_kvp[(size_t)(bh * SPLITS + p) * 4096 + idx];
        g_kv[(size_t)bh * 4096 + idx] = s;
    }
    if (tid < 64) {
        float s = 0.f;
        #pragma unroll
        for (int p = 0; p < SPLITS; p++)
            s += g_ksump[(size_t)(bh * SPLITS + p) * 64 + tid];
        g_ksum[bh * 64 + tid] = s;
    }
}

// ============================================================
// Phase 3: out[n,e] = (q[n,:] @ kv[:,e]) / (q[n,:]·ksum + 1e-6)
// 4x4 microtile per thread; written into (B,N,C) layout.
// ============================================================
__global__ __launch_bounds__(256) void q_apply_kernel(const float* __restrict__ qkv)
{
    int bh = blockIdx.x; int b = bh >> 4, h = bh & 15;
    int nb = blockIdx.y;
    int tid = threadIdx.x;

    __shared__ float kvs[64][68];   // kvs[d][e]
    __shared__ float qs [64][68];   // qs[r][d]
    __shared__ float kss[64];

    {
        const float* src = g_kv + (size_t)bh * 4096;
        for (int l = tid; l < 1024; l += 256) {
            int d = l >> 4; int e = (l & 15) * 4;
            *reinterpret_cast<float4*>(&kvs[d][e]) =
                *reinterpret_cast<const float4*>(src + d * 64 + e);
        }
    }
    if (tid < 64) kss[tid] = g_ksum[bh * 64 + tid];

    const float* qbase = qkv + ((size_t)b * N_ + nb * 64) * N1 + h * 64;
    for (int l = tid; l < 1024; l += 256) {
        int r = l >> 4; int c = (l & 15) * 4;
        *reinterpret_cast<float4*>(&qs[r][c]) =
            *reinterpret_cast<const float4*>(qbase + (size_t)r * N1 + c);
    }
    __syncthreads();

    const int r0 = (tid >> 4) * 4;
    const int e0 = (tid & 15) * 4;

    float acc[4][4] = {};
    float nacc[4] = {0.f, 0.f, 0.f, 0.f};

    #pragma unroll 8
    for (int d = 0; d < 64; d++) {
        float qv[4], kvr[4];
        #pragma unroll
        for (int i = 0; i < 4; i++) qv[i] = qs[r0 + i][d];
        *reinterpret_cast<float4*>(kvr) = *reinterpret_cast<float4*>(&kvs[d][e0]);
        float ksd = kss[d];
        #pragma unroll
        for (int i = 0; i < 4; i++) {
            nacc[i] += qv[i] * ksd;
            #pragma unroll
            for (int j = 0; j < 4; j++)
                acc[i][j] += qv[i] * kvr[j];
        }
    }

    #pragma unroll
    for (int i = 0; i < 4; i++) {
        float inv = 1.f / (nacc[i] + 1e-6f);
        float4 v = make_float4(acc[i][0] * inv, acc[i][1] * inv,
                               acc[i][2] * inv, acc[i][3] * inv);
        int n = nb * 64 + r0 + i;
        *reinterpret_cast<float4*>(
            &g_attn[((size_t)b * N_ + n) * C_ + h * 64 + e0]) = v;
    }
}

// ============================================================
extern "C" void kernel_launch(void* const* d_in, const int* in_sizes, int n_in,
                              void* d_out, int out_size)
{
    const float* x     = (const float*)d_in[0];
    const float* W_qkv = (const float*)d_in[1];
    const float* W_out = (const float*)d_in[2];
    const float* b_out = (const float*)d_in[3];
    float* out = (float*)d_out;

    float *p_qkv, *p_attn;
    cudaGetSymbolAddress((void**)&p_qkv,  g_qkv);
    cudaGetSymbolAddress((void**)&p_attn, g_attn);

    // opt-in to >48KB dynamic smem (idempotent; host-side, not captured)
    cudaFuncSetAttribute(tf32gemm<1>, cudaFuncAttributeMaxDynamicSharedMemorySize, GEMM_SMEM);
    cudaFuncSetAttribute(tf32gemm<2>, cudaFuncAttributeMaxDynamicSharedMemorySize, GEMM_SMEM);

    // 1) qkv = x @ W_qkv (tf32 tensor cores), elu+1 fused on q,k columns
    tf32gemm<1><<<dim3(N1 / 128, M1 / 256), 256, GEMM_SMEM>>>(x, W_qkv, p_qkv, M1, N1, C_, nullptr);
    // 2) kv / ksum split-K partials + reduce (fp32 exact)
    kv_partial_kernel<<<dim3(64, SPLITS), 256>>>(p_qkv);
    kv_reduce_kernel<<<64, 256>>>();
    // 3) numerator / normalizer / divide -> (B,N,C)
    q_apply_kernel<<<dim3(64, 64), 256>>>(p_qkv);
    // 4) out = attn @ W_out + b_out (tf32 tensor cores)
    tf32gemm<2><<<dim3(C_ / 128, M1 / 256), 256, GEMM_SMEM>>>(p_attn, W_out, out, M1, C_, C_, b_out);
}

// round 11
// speedup vs baseline: 1.9354x; 1.9354x over previous
#include <cuda_runtime.h>
#include <cuda_fp16.h>
#include <cstdint>

#define B_ 4
#define N_ 4096
#define C_ 1024
#define H_ 16
#define D_ 64
#define M1 (B_*N_)      // 16384 rows
#define N1 (3*C_)       // 3072 qkv cols
#define SPLITS 16
#define CHUNK (N_/SPLITS) // 256 rows per split

// ---- scratch (no allocs allowed; __device__ globals) ----
__device__ float  g_qkv [(size_t)M1 * N1];           // 201 MB fp32 qkv
__device__ __half g_xh  [(size_t)M1 * C_];           //  32 MB x as half
__device__ __half g_attnh[(size_t)M1 * C_];          //  32 MB attn as half
__device__ uint32_t g_wqkvP[(size_t)(C_/2) * N1];    //   6 MB W_qkv k-pair-packed half2
__device__ uint32_t g_woutP[(size_t)(C_/2) * C_];    //   2 MB W_out  k-pair-packed half2
__device__ float g_kvp [64 * SPLITS * 64 * 64];
__device__ float g_ksump[64 * SPLITS * 64];
__device__ float g_kv  [64 * 64 * 64];
__device__ float g_ksum[64 * 64];

// ============================================================
// helpers
// ============================================================
__device__ __forceinline__ uint32_t h2u(__half2 h) {
    return *reinterpret_cast<uint32_t*>(&h);
}

__device__ __forceinline__ void mma_f16(float* c, const uint32_t* a, const uint32_t* b) {
    asm volatile(
        "mma.sync.aligned.m16n8k16.row.col.f32.f16.f16.f32 "
        "{%0,%1,%2,%3}, {%4,%5,%6,%7}, {%8,%9}, {%0,%1,%2,%3};"
        : "+f"(c[0]), "+f"(c[1]), "+f"(c[2]), "+f"(c[3])
        : "r"(a[0]), "r"(a[1]), "r"(a[2]), "r"(a[3]), "r"(b[0]), "r"(b[1]));
}

__device__ __forceinline__ void cp16s(void* smem_dst, const void* gmem_src) {
    asm volatile("cp.async.cg.shared.global [%0], [%1], 16;"
        :: "r"((uint32_t)__cvta_generic_to_shared(smem_dst)), "l"(gmem_src));
}
#define CP_COMMIT() asm volatile("cp.async.commit_group;" ::)
#define CP_WAIT(n)  asm volatile("cp.async.wait_group %0;" :: "n"(n))

// ============================================================
// fp16 tensor-core GEMM: C[M,N] = A[M,K] @ B[K,N], A half
// row-major, B k-pair-packed half2 [K/2][N] (u32), C fp32.
// 128x128 CTA tile, BK=32 (2 k-steps of m16n8k16), 3-stage
// cp.async pipeline, 256 threads (8 warps, 2x4), warp tile
// 64x32 (4x4 MMAs per k-step). fp32 accumulate.
// A smem: half[128][40]  (pitch 40 -> conflict-free frags)
// B smem: u32 [16][136]  (pitch 136 -> conflict-free frags)
// MODE 1: elu(x)+1 on cols < 2048.  MODE 2: += bias[col].
// Requires M%128==0, N%128==0, K%32==0, K>=96.
// ============================================================
#define BKH 32
#define APITCH 40                       // halves per A row
#define BPITCH 136                      // u32 per B row
#define A_BYTES (128 * APITCH * 2)      // 10240
#define B_BYTES (16 * BPITCH * 4)       // 8704
#define STG_BYTES (A_BYTES + B_BYTES)   // 18944
#define NSTG 3
#define GEMM_SMEM (NSTG * STG_BYTES)    // 56832

template<int MODE>
__global__ __launch_bounds__(256, 2) void hgemm(
    const __half* __restrict__ A, const uint32_t* __restrict__ Bp,
    float* __restrict__ C, int M, int N, int K,
    const float* __restrict__ bias)
{
    extern __shared__ char smem[];

    const int tid  = threadIdx.x;
    const int lane = tid & 31;
    const int warp = tid >> 5;
    const int wr = warp >> 2;            // 0..1  (64-row slabs)
    const int wc = warp & 3;             // 0..3  (32-col slabs)
    const int bx = blockIdx.x, by = blockIdx.y;
    const int la3 = lane & 3;
    const int l4  = lane >> 2;

    const __half*   Ab = A  + (size_t)(by * 128) * K;
    const uint32_t* Bb = Bp + bx * 128;

    // stage s: A at smem + s*STG_BYTES (half[128][40]),
    //          B at smem + s*STG_BYTES + A_BYTES (u32[16][136])
    #define LOAD_STAGE(s, kk)                                                   \
        do {                                                                    \
            char* as_ = smem + (s) * STG_BYTES;                                 \
            char* bs_ = as_ + A_BYTES;                                          \
            _Pragma("unroll")                                                   \
            for (int i = 0; i < 2; i++) {                                       \
                int j = tid + 256 * i;                                          \
                int m = j >> 2, c8 = j & 3;          /* 8 halves per chunk */   \
                cp16s(as_ + m * (APITCH * 2) + c8 * 16,                         \
                      Ab + (size_t)m * K + (kk) + c8 * 8);                      \
            }                                                                   \
            _Pragma("unroll")                                                   \
            for (int i = 0; i < 2; i++) {                                       \
                int j = tid + 256 * i;                                          \
                int kp = j >> 5, c4 = j & 31;        /* 4 u32 per chunk */      \
                cp16s(bs_ + kp * (BPITCH * 4) + c4 * 16,                        \
                      Bb + (size_t)((kk) / 2 + kp) * N + c4 * 4);               \
            }                                                                   \
            CP_COMMIT();                                                        \
        } while (0)

    const int nT = K / BKH;
    LOAD_STAGE(0, 0);
    LOAD_STAGE(1, BKH);

    float acc[4][4][4] = {};

    for (int t = 0; t < nT; t++) {
        if (t + 1 < nT) { CP_WAIT(1); } else { CP_WAIT(0); }
        __syncthreads();

        if (t + 2 < nT) {
            LOAD_STAGE((t + 2) % NSTG, (t + 2) * BKH);
        }

        const char* as_ = smem + (t % NSTG) * STG_BYTES;
        const char* bs_ = as_ + A_BYTES;

        #pragma unroll
        for (int ks = 0; ks < BKH; ks += 16) {       // 2 k-steps of 16
            const int ks2 = ks >> 1;                 // k-pair row offset
            uint32_t af[4][4], bf[4][2];
            #pragma unroll
            for (int mt = 0; mt < 4; mt++) {
                int rb = wr * 64 + mt * 16 + l4;
                const char* r0 = as_ + rb * (APITCH * 2);
                af[mt][0] = *reinterpret_cast<const uint32_t*>(r0 + (ks + la3 * 2) * 2);
                af[mt][1] = *reinterpret_cast<const uint32_t*>(r0 + 8 * (APITCH * 2) + (ks + la3 * 2) * 2);
                af[mt][2] = *reinterpret_cast<const uint32_t*>(r0 + (ks + 8 + la3 * 2) * 2);
                af[mt][3] = *reinterpret_cast<const uint32_t*>(r0 + 8 * (APITCH * 2) + (ks + 8 + la3 * 2) * 2);
            }
            #pragma unroll
            for (int nt = 0; nt < 4; nt++) {
                int nb = wc * 32 + nt * 8 + l4;
                bf[nt][0] = *reinterpret_cast<const uint32_t*>(bs_ + (ks2 + la3)     * (BPITCH * 4) + nb * 4);
                bf[nt][1] = *reinterpret_cast<const uint32_t*>(bs_ + (ks2 + 4 + la3) * (BPITCH * 4) + nb * 4);
            }
            #pragma unroll
            for (int mt = 0; mt < 4; mt++)
                #pragma unroll
                for (int nt = 0; nt < 4; nt++)
                    mma_f16(acc[mt][nt], af[mt], bf[nt]);
        }
        __syncthreads();
    }

    // epilogue (same C-frag mapping as m16n8k8)
    #pragma unroll
    for (int mt = 0; mt < 4; mt++) {
        #pragma unroll
        for (int nt = 0; nt < 4; nt++) {
            int row = by * 128 + wr * 64 + mt * 16 + l4;
            int col = bx * 128 + wc * 32 + nt * 8 + la3 * 2;
            float v0 = acc[mt][nt][0], v1 = acc[mt][nt][1];
            float v2 = acc[mt][nt][2], v3 = acc[mt][nt][3];
            if (MODE == 1) {
                if (col < 2 * C_) {   // q,k columns: elu(x)+1
                    v0 = (v0 > 0.f) ? (v0 + 1.f) : __expf(v0);
                    v1 = (v1 > 0.f) ? (v1 + 1.f) : __expf(v1);
                    v2 = (v2 > 0.f) ? (v2 + 1.f) : __expf(v2);
                    v3 = (v3 > 0.f) ? (v3 + 1.f) : __expf(v3);
                }
            } else if (MODE == 2) {
                float b0 = bias[col], b1 = bias[col + 1];
                v0 += b0; v1 += b1; v2 += b0; v3 += b1;
            }
            *reinterpret_cast<float2*>(C + (size_t)row * N + col)       = make_float2(v0, v1);
            *reinterpret_cast<float2*>(C + (size_t)(row + 8) * N + col) = make_float2(v2, v3);
        }
    }
}

// ============================================================
// conversion kernels
// ============================================================
// fp32 -> half, elementwise (for x)
__global__ __launch_bounds__(256) void conv_half_kernel(
    const float* __restrict__ in, __half* __restrict__ out, int n4)
{
    int i = blockIdx.x * blockDim.x + threadIdx.x;
    if (i < n4) {
        float4 v = reinterpret_cast<const float4*>(in)[i];
        uint32_t lo = h2u(__floats2half2_rn(v.x, v.y));
        uint32_t hi = h2u(__floats2half2_rn(v.z, v.w));
        reinterpret_cast<uint2*>(out)[i] = make_uint2(lo, hi);
    }
}

// fp32 W[K][N] -> k-pair-packed half2 u32 [K/2][N]
__global__ __launch_bounds__(256) void conv_pack_kernel(
    const float* __restrict__ W, uint32_t* __restrict__ out, int K, int N)
{
    int i = blockIdx.x * blockDim.x + threadIdx.x;
    int total = (K / 2) * N;
    if (i < total) {
        int kp = i / N, n = i % N;
        float lo = W[(size_t)(2 * kp) * N + n];
        float hi = W[(size_t)(2 * kp + 1) * N + n];
        out[i] = h2u(__floats2half2_rn(lo, hi));
    }
}

// ============================================================
// Phase 2: per (b,h) split-K partials of kv[d][e] = sum_n k*v
// and ksum[d] = sum_n k.  Deterministic (no atomics).
// ============================================================
__global__ __launch_bounds__(256) void kv_partial_kernel(const float* __restrict__ qkv)
{
    int bh = blockIdx.x;
    int b = bh >> 4, h = bh & 15;
    int n0 = blockIdx.y * CHUNK;
    int tid = threadIdx.x;
    int d0 = (tid >> 4) * 4, e0 = (tid & 15) * 4;

    __shared__ float ks[32][64];
    __shared__ float vs[32][64];

    float acc[4][4] = {};
    float ksacc[4] = {0.f, 0.f, 0.f, 0.f};

    const float* base = qkv + (size_t)b * N_ * N1 + h * 64;

    for (int nt = 0; nt < CHUNK; nt += 32) {
        for (int l = tid; l < 512; l += 256) {
            int r = l >> 4; int c = (l & 15) * 4;
            size_t off = (size_t)(n0 + nt + r) * N1 + c;
            *reinterpret_cast<float4*>(&ks[r][c]) =
                *reinterpret_cast<const float4*>(base + 1024 + off);
            *reinterpret_cast<float4*>(&vs[r][c]) =
                *reinterpret_cast<const float4*>(base + 2048 + off);
        }
        __syncthreads();
        #pragma unroll 4
        for (int r = 0; r < 32; r++) {
            float kr[4], vr[4];
            *reinterpret_cast<float4*>(kr) = *reinterpret_cast<float4*>(&ks[r][d0]);
            *reinterpret_cast<float4*>(vr) = *reinterpret_cast<float4*>(&vs[r][e0]);
            #pragma unroll
            for (int i = 0; i < 4; i++)
                #pragma unroll
                for (int j = 0; j < 4; j++)
                    acc[i][j] += kr[i] * vr[j];
            if (e0 == 0) {
                #pragma unroll
                for (int i = 0; i < 4; i++) ksacc[i] += kr[i];
            }
        }
        __syncthreads();
    }

    float* kvp = g_kvp + (size_t)(bh * SPLITS + blockIdx.y) * 4096;
    #pragma unroll
    for (int i = 0; i < 4; i++)
        #pragma unroll
        for (int j = 0; j < 4; j++)
            kvp[(d0 + i) * 64 + e0 + j] = acc[i][j];
    if (e0 == 0) {
        float* ksp = g_ksump + (size_t)(bh * SPLITS + blockIdx.y) * 64;
        #pragma unroll
        for (int i = 0; i < 4; i++) ksp[d0 + i] = ksacc[i];
    }
}

__global__ __launch_bounds__(256) void kv_reduce_kernel()
{
    int bh = blockIdx.x; int tid = threadIdx.x;
    for (int idx = tid; idx < 4096; idx += 256) {
        float s = 0.f;
        #pragma unroll
        for (int p = 0; p < SPLITS; p++)
            s += g_kvp[(size_t)(bh * SPLITS + p) * 4096 + idx];
        g_kv[(size_t)bh * 4096 + idx] = s;
    }
    if (tid < 64) {
        float s = 0.f;
        #pragma unroll
        for (int p = 0; p < SPLITS; p++)
            s += g_ksump[(size_t)(bh * SPLITS + p) * 64 + tid];
        g_ksum[bh * 64 + tid] = s;
    }
}

// ============================================================
// Phase 3: out[n,e] = (q[n,:] @ kv[:,e]) / (q[n,:]·ksum + 1e-6)
// fp32 math; stores half (feeds fp16 GEMM2 A directly).
// ============================================================
__global__ __launch_bounds__(256) void q_apply_kernel(const float* __restrict__ qkv)
{
    int bh = blockIdx.x; int b = bh >> 4, h = bh & 15;
    int nb = blockIdx.y;
    int tid = threadIdx.x;

    __shared__ float kvs[64][68];   // kvs[d][e]
    __shared__ float qs [64][68];   // qs[r][d]
    __shared__ float kss[64];

    {
        const float* src = g_kv + (size_t)bh * 4096;
        for (int l = tid; l < 1024; l += 256) {
            int d = l >> 4; int e = (l & 15) * 4;
            *reinterpret_cast<float4*>(&kvs[d][e]) =
                *reinterpret_cast<const float4*>(src + d * 64 + e);
        }
    }
    if (tid < 64) kss[tid] = g_ksum[bh * 64 + tid];

    const float* qbase = qkv + ((size_t)b * N_ + nb * 64) * N1 + h * 64;
    for (int l = tid; l < 1024; l += 256) {
        int r = l >> 4; int c = (l & 15) * 4;
        *reinterpret_cast<float4*>(&qs[r][c]) =
            *reinterpret_cast<const float4*>(qbase + (size_t)r * N1 + c);
    }
    __syncthreads();

    const int r0 = (tid >> 4) * 4;
    const int e0 = (tid & 15) * 4;

    float acc[4][4] = {};
    float nacc[4] = {0.f, 0.f, 0.f, 0.f};

    #pragma unroll 8
    for (int d = 0; d < 64; d++) {
        float qv[4], kvr[4];
        #pragma unroll
        for (int i = 0; i < 4; i++) qv[i] = qs[r0 + i][d];
        *reinterpret_cast<float4*>(kvr) = *reinterpret_cast<float4*>(&kvs[d][e0]);
        float ksd = kss[d];
        #pragma unroll
        for (int i = 0; i < 4; i++) {
            nacc[i] += qv[i] * ksd;
            #pragma unroll
            for (int j = 0; j < 4; j++)
                acc[i][j] += qv[i] * kvr[j];
        }
    }

    #pragma unroll
    for (int i = 0; i < 4; i++) {
        float inv = 1.f / (nacc[i] + 1e-6f);
        uint32_t lo = h2u(__floats2half2_rn(acc[i][0] * inv, acc[i][1] * inv));
        uint32_t hi = h2u(__floats2half2_rn(acc[i][2] * inv, acc[i][3] * inv));
        int n = nb * 64 + r0 + i;
        *reinterpret_cast<uint2*>(
            &g_attnh[((size_t)b * N_ + n) * C_ + h * 64 + e0]) = make_uint2(lo, hi);
    }
}

// ============================================================
extern "C" void kernel_launch(void* const* d_in, const int* in_sizes, int n_in,
                              void* d_out, int out_size)
{
    const float* x     = (const float*)d_in[0];
    const float* W_qkv = (const float*)d_in[1];
    const float* W_out = (const float*)d_in[2];
    const float* b_out = (const float*)d_in[3];
    float* out = (float*)d_out;

    float *p_qkv;
    __half *p_xh, *p_attnh;
    uint32_t *p_wqkvP, *p_woutP;
    cudaGetSymbolAddress((void**)&p_qkv,   g_qkv);
    cudaGetSymbolAddress((void**)&p_xh,    g_xh);
    cudaGetSymbolAddress((void**)&p_attnh, g_attnh);
    cudaGetSymbolAddress((void**)&p_wqkvP, g_wqkvP);
    cudaGetSymbolAddress((void**)&p_woutP, g_woutP);

    cudaFuncSetAttribute(hgemm<1>, cudaFuncAttributeMaxDynamicSharedMemorySize, GEMM_SMEM);
    cudaFuncSetAttribute(hgemm<2>, cudaFuncAttributeMaxDynamicSharedMemorySize, GEMM_SMEM);

    // 0) convert inputs to fp16 (x elementwise; weights k-pair packed)
    conv_half_kernel<<<(M1 * C_ / 4 + 255) / 256, 256>>>(x, p_xh, M1 * C_ / 4);
    conv_pack_kernel<<<((C_ / 2) * N1 + 255) / 256, 256>>>(W_qkv, p_wqkvP, C_, N1);
    conv_pack_kernel<<<((C_ / 2) * C_ + 255) / 256, 256>>>(W_out, p_woutP, C_, C_);

    // 1) qkv = x @ W_qkv (fp16 tensor cores, fp32 accum), elu+1 fused
    hgemm<1><<<dim3(N1 / 128, M1 / 128), 256, GEMM_SMEM>>>(p_xh, p_wqkvP, p_qkv, M1, N1, C_, nullptr);
    // 2) kv / ksum split-K partials + reduce (fp32 exact)
    kv_partial_kernel<<<dim3(64, SPLITS), 256>>>(p_qkv);
    kv_reduce_kernel<<<64, 256>>>();
    // 3) numerator / normalizer / divide -> (B,N,C) half
    q_apply_kernel<<<dim3(64, 64), 256>>>(p_qkv);
    // 4) out = attn @ W_out + b_out (fp16 tensor cores, fp32 accum)
    hgemm<2><<<dim3(C_ / 128, M1 / 128), 256, GEMM_SMEM>>>(p_attnh, p_woutP, out, M1, C_, C_, b_out);
}

// round 14
// speedup vs baseline: 1.9699x; 1.0178x over previous
#include <cuda_runtime.h>
#include <cuda_fp16.h>
#include <cstdint>

#define B_ 4
#define N_ 4096
#define C_ 1024
#define H_ 16
#define D_ 64
#define M1 (B_*N_)      // 16384 rows
#define N1 (3*C_)       // 3072 qkv cols
#define SPLITS 16
#define CHUNK (N_/SPLITS) // 256 rows per split

// ---- scratch (no allocs allowed; __device__ globals) ----
__device__ float  g_qkv [(size_t)M1 * N1];           // 201 MB fp32 qkv
__device__ __half g_xh  [(size_t)M1 * C_];           //  32 MB x as half
__device__ __half g_attnh[(size_t)M1 * C_];          //  32 MB attn as half
__device__ uint32_t g_wqkvP[(size_t)(C_/2) * N1];    //   6 MB W_qkv k-pair-packed half2
__device__ uint32_t g_woutP[(size_t)(C_/2) * C_];    //   2 MB W_out  k-pair-packed half2
__device__ float g_kvp [64 * SPLITS * 64 * 64];
__device__ float g_ksump[64 * SPLITS * 64];
__device__ float g_kv  [64 * 64 * 64];
__device__ float g_ksum[64 * 64];

// ============================================================
// helpers
// ============================================================
__device__ __forceinline__ uint32_t h2u(__half2 h) {
    return *reinterpret_cast<uint32_t*>(&h);
}

__device__ __forceinline__ void mma_f16(float* c, const uint32_t* a, const uint32_t* b) {
    asm volatile(
        "mma.sync.aligned.m16n8k16.row.col.f32.f16.f16.f32 "
        "{%0,%1,%2,%3}, {%4,%5,%6,%7}, {%8,%9}, {%0,%1,%2,%3};"
        : "+f"(c[0]), "+f"(c[1]), "+f"(c[2]), "+f"(c[3])
        : "r"(a[0]), "r"(a[1]), "r"(a[2]), "r"(a[3]), "r"(b[0]), "r"(b[1]));
}

__device__ __forceinline__ void cp16s(void* smem_dst, const void* gmem_src) {
    asm volatile("cp.async.cg.shared.global [%0], [%1], 16;"
        :: "r"((uint32_t)__cvta_generic_to_shared(smem_dst)), "l"(gmem_src));
}
#define CP_COMMIT() asm volatile("cp.async.commit_group;" ::)
#define CP_WAIT(n)  asm volatile("cp.async.wait_group %0;" :: "n"(n))

// ============================================================
// fp16 tensor-core GEMM: C[M,N] = A[M,K] @ B[K,N], A half
// row-major, B k-pair-packed half2 [K/2][N] (u32), C fp32.
// 128x128 CTA tile, BK=32, 4-stage cp.async pipeline,
// 128 threads (4 warps, 2x2), warp tile 64x64
// (4x8 m16n8k16 per k-step). fp32 accumulate.
// A smem: half[128][40]  (pitch 40 -> conflict-free frags)
// B smem: u32 [16][136]  (pitch 136 -> conflict-free frags)
// MODE 1: elu(x)+1 on cols < 2048.  MODE 2: += bias[col].
// Requires M%128==0, N%128==0, K%32==0, K>=128.
// ============================================================
#define BKH 32
#define APITCH 40                       // halves per A row
#define BPITCH 136                      // u32 per B row
#define A_BYTES (128 * APITCH * 2)      // 10240
#define B_BYTES (16 * BPITCH * 4)       // 8704
#define STG_BYTES (A_BYTES + B_BYTES)   // 18944
#define NSTG 4
#define GEMM_SMEM (NSTG * STG_BYTES)    // 75776

template<int MODE>
__global__ __launch_bounds__(128, 2) void hgemm(
    const __half* __restrict__ A, const uint32_t* __restrict__ Bp,
    float* __restrict__ C, int M, int N, int K,
    const float* __restrict__ bias)
{
    extern __shared__ char smem[];

    const int tid  = threadIdx.x;
    const int lane = tid & 31;
    const int warp = tid >> 5;
    const int wr = warp >> 1;            // 0..1  (64-row slabs)
    const int wc = warp & 1;             // 0..1  (64-col slabs)
    const int bx = blockIdx.x, by = blockIdx.y;
    const int la3 = lane & 3;
    const int l4  = lane >> 2;

    const __half*   Ab = A  + (size_t)(by * 128) * K;
    const uint32_t* Bb = Bp + bx * 128;

    // stage s: A at smem + s*STG_BYTES (half[128][40]),
    //          B at smem + s*STG_BYTES + A_BYTES (u32[16][136])
    #define LOAD_STAGE(s, kk)                                                   \
        do {                                                                    \
            char* as_ = smem + (s) * STG_BYTES;                                 \
            char* bs_ = as_ + A_BYTES;                                          \
            _Pragma("unroll")                                                   \
            for (int i = 0; i < 4; i++) {                                       \
                int j = tid + 128 * i;                                          \
                int m = j >> 2, c8 = j & 3;          /* 8 halves per chunk */   \
                cp16s(as_ + m * (APITCH * 2) + c8 * 16,                         \
                      Ab + (size_t)m * K + (kk) + c8 * 8);                      \
            }                                                                   \
            _Pragma("unroll")                                                   \
            for (int i = 0; i < 4; i++) {                                       \
                int j = tid + 128 * i;                                          \
                int kp = j >> 5, c4 = j & 31;        /* 4 u32 per chunk */      \
                cp16s(bs_ + kp * (BPITCH * 4) + c4 * 16,                        \
                      Bb + (size_t)((kk) / 2 + kp) * N + c4 * 4);               \
            }                                                                   \
            CP_COMMIT();                                                        \
        } while (0)

    const int nT = K / BKH;
    LOAD_STAGE(0, 0);
    LOAD_STAGE(1, BKH);
    LOAD_STAGE(2, 2 * BKH);

    float acc[4][8][4] = {};

    for (int t = 0; t < nT; t++) {
        if (t + 2 < nT) { CP_WAIT(2); }
        else if (t + 1 < nT) { CP_WAIT(1); }
        else { CP_WAIT(0); }
        __syncthreads();

        // prefetch t+3 into the stage freed by compute(t-1)
        if (t + 3 < nT) {
            LOAD_STAGE((t + 3) % NSTG, (t + 3) * BKH);
        }

        const char* as_ = smem + (t % NSTG) * STG_BYTES;
        const char* bs_ = as_ + A_BYTES;

        #pragma unroll
        for (int ks = 0; ks < BKH; ks += 16) {       // 2 k-steps of 16
            const int ks2 = ks >> 1;                 // k-pair row offset
            uint32_t af[4][4], bf[8][2];
            #pragma unroll
            for (int mt = 0; mt < 4; mt++) {
                int rb = wr * 64 + mt * 16 + l4;
                const char* r0 = as_ + rb * (APITCH * 2);
                af[mt][0] = *reinterpret_cast<const uint32_t*>(r0 + (ks + la3 * 2) * 2);
                af[mt][1] = *reinterpret_cast<const uint32_t*>(r0 + 8 * (APITCH * 2) + (ks + la3 * 2) * 2);
                af[mt][2] = *reinterpret_cast<const uint32_t*>(r0 + (ks + 8 + la3 * 2) * 2);
                af[mt][3] = *reinterpret_cast<const uint32_t*>(r0 + 8 * (APITCH * 2) + (ks + 8 + la3 * 2) * 2);
            }
            #pragma unroll
            for (int nt = 0; nt < 8; nt++) {
                int nb = wc * 64 + nt * 8 + l4;
                bf[nt][0] = *reinterpret_cast<const uint32_t*>(bs_ + (ks2 + la3)     * (BPITCH * 4) + nb * 4);
                bf[nt][1] = *reinterpret_cast<const uint32_t*>(bs_ + (ks2 + 4 + la3) * (BPITCH * 4) + nb * 4);
            }
            #pragma unroll
            for (int mt = 0; mt < 4; mt++)
                #pragma unroll
                for (int nt = 0; nt < 8; nt++)
                    mma_f16(acc[mt][nt], af[mt], bf[nt]);
        }
        __syncthreads();
    }

    // epilogue
    #pragma unroll
    for (int mt = 0; mt < 4; mt++) {
        #pragma unroll
        for (int nt = 0; nt < 8; nt++) {
            int row = by * 128 + wr * 64 + mt * 16 + l4;
            int col = bx * 128 + wc * 64 + nt * 8 + la3 * 2;
            float v0 = acc[mt][nt][0], v1 = acc[mt][nt][1];
            float v2 = acc[mt][nt][2], v3 = acc[mt][nt][3];
            if (MODE == 1) {
                if (col < 2 * C_) {   // q,k columns: elu(x)+1
                    v0 = (v0 > 0.f) ? (v0 + 1.f) : __expf(v0);
                    v1 = (v1 > 0.f) ? (v1 + 1.f) : __expf(v1);
                    v2 = (v2 > 0.f) ? (v2 + 1.f) : __expf(v2);
                    v3 = (v3 > 0.f) ? (v3 + 1.f) : __expf(v3);
                }
            } else if (MODE == 2) {
                float b0 = bias[col], b1 = bias[col + 1];
                v0 += b0; v1 += b1; v2 += b0; v3 += b1;
            }
            *reinterpret_cast<float2*>(C + (size_t)row * N + col)       = make_float2(v0, v1);
            *reinterpret_cast<float2*>(C + (size_t)(row + 8) * N + col) = make_float2(v2, v3);
        }
    }
}

// ============================================================
// conversion kernels
// ============================================================
// fp32 -> half, elementwise (for x)
__global__ __launch_bounds__(256) void conv_half_kernel(
    const float* __restrict__ in, __half* __restrict__ out, int n4)
{
    int i = blockIdx.x * blockDim.x + threadIdx.x;
    if (i < n4) {
        float4 v = reinterpret_cast<const float4*>(in)[i];
        uint32_t lo = h2u(__floats2half2_rn(v.x, v.y));
        uint32_t hi = h2u(__floats2half2_rn(v.z, v.w));
        reinterpret_cast<uint2*>(out)[i] = make_uint2(lo, hi);
    }
}

// fp32 W[K][N] -> k-pair-packed half2 u32 [K/2][N]
__global__ __launch_bounds__(256) void conv_pack_kernel(
    const float* __restrict__ W, uint32_t* __restrict__ out, int K, int N)
{
    int i = blockIdx.x * blockDim.x + threadIdx.x;
    int total = (K / 2) * N;
    if (i < total) {
        int kp = i / N, n = i % N;
        float lo = W[(size_t)(2 * kp) * N + n];
        float hi = W[(size_t)(2 * kp + 1) * N + n];
        out[i] = h2u(__floats2half2_rn(lo, hi));
    }
}

// ============================================================
// Phase 2: per (b,h) split-K partials of kv[d][e] = sum_n k*v
// and ksum[d] = sum_n k.  Deterministic (no atomics).
// ============================================================
__global__ __launch_bounds__(256) void kv_partial_kernel(const float* __restrict__ qkv)
{
    int bh = blockIdx.x;
    int b = bh >> 4, h = bh & 15;
    int n0 = blockIdx.y * CHUNK;
    int tid = threadIdx.x;
    int d0 = (tid >> 4) * 4, e0 = (tid & 15) * 4;

    __shared__ float ks[32][64];
    __shared__ float vs[32][64];

    float acc[4][4] = {};
    float ksacc[4] = {0.f, 0.f, 0.f, 0.f};

    const float* base = qkv + (size_t)b * N_ * N1 + h * 64;

    for (int nt = 0; nt < CHUNK; nt += 32) {
        for (int l = tid; l < 512; l += 256) {
            int r = l >> 4; int c = (l & 15) * 4;
            size_t off = (size_t)(n0 + nt + r) * N1 + c;
            *reinterpret_cast<float4*>(&ks[r][c]) =
                *reinterpret_cast<const float4*>(base + 1024 + off);
            *reinterpret_cast<float4*>(&vs[r][c]) =
                *reinterpret_cast<const float4*>(base + 2048 + off);
        }
        __syncthreads();
        #pragma unroll 4
        for (int r = 0; r < 32; r++) {
            float kr[4], vr[4];
            *reinterpret_cast<float4*>(kr) = *reinterpret_cast<float4*>(&ks[r][d0]);
            *reinterpret_cast<float4*>(vr) = *reinterpret_cast<float4*>(&vs[r][e0]);
            #pragma unroll
            for (int i = 0; i < 4; i++)
                #pragma unroll
                for (int j = 0; j < 4; j++)
                    acc[i][j] += kr[i] * vr[j];
            if (e0 == 0) {
                #pragma unroll
                for (int i = 0; i < 4; i++) ksacc[i] += kr[i];
            }
        }
        __syncthreads();
    }

    float* kvp = g_kvp + (size_t)(bh * SPLITS + blockIdx.y) * 4096;
    #pragma unroll
    for (int i = 0; i < 4; i++)
        #pragma unroll
        for (int j = 0; j < 4; j++)
            kvp[(d0 + i) * 64 + e0 + j] = acc[i][j];
    if (e0 == 0) {
        float* ksp = g_ksump + (size_t)(bh * SPLITS + blockIdx.y) * 64;
        #pragma unroll
        for (int i = 0; i < 4; i++) ksp[d0 + i] = ksacc[i];
    }
}

__global__ __launch_bounds__(256) void kv_reduce_kernel()
{
    int bh = blockIdx.x; int tid = threadIdx.x;
    for (int idx = tid; idx < 4096; idx += 256) {
        float s = 0.f;
        #pragma unroll
        for (int p = 0; p < SPLITS; p++)
            s += g_kvp[(size_t)(bh * SPLITS + p) * 4096 + idx];
        g_kv[(size_t)bh * 4096 + idx] = s;
    }
    if (tid < 64) {
        float s = 0.f;
        #pragma unroll
        for (int p = 0; p < SPLITS; p++)
            s += g_ksump[(size_t)(bh * SPLITS + p) * 64 + tid];
        g_ksum[bh * 64 + tid] = s;
    }
}

// ============================================================
// Phase 3: out[n,e] = (q[n,:] @ kv[:,e]) / (q[n,:]·ksum + 1e-6)
// fp32 math; stores half (feeds fp16 GEMM2 A directly).
// ============================================================
__global__ __launch_bounds__(256) void q_apply_kernel(const float* __restrict__ qkv)
{
    int bh = blockIdx.x; int b = bh >> 4, h = bh & 15;
    int nb = blockIdx.y;
    int tid = threadIdx.x;

    __shared__ float kvs[64][68];   // kvs[d][e]
    __shared__ float qs [64][68];   // qs[r][d]
    __shared__ float kss[64];

    {
        const float* src = g_kv + (size_t)bh * 4096;
        for (int l = tid; l < 1024; l += 256) {
            int d = l >> 4; int e = (l & 15) * 4;
            *reinterpret_cast<float4*>(&kvs[d][e]) =
                *reinterpret_cast<const float4*>(src + d * 64 + e);
        }
    }
    if (tid < 64) kss[tid] = g_ksum[bh * 64 + tid];

    const float* qbase = qkv + ((size_t)b * N_ + nb * 64) * N1 + h * 64;
    for (int l = tid; l < 1024; l += 256) {
        int r = l >> 4; int c = (l & 15) * 4;
        *reinterpret_cast<float4*>(&qs[r][c]) =
            *reinterpret_cast<const float4*>(qbase + (size_t)r * N1 + c);
    }
    __syncthreads();

    const int r0 = (tid >> 4) * 4;
    const int e0 = (tid & 15) * 4;

    float acc[4][4] = {};
    float nacc[4] = {0.f, 0.f, 0.f, 0.f};

    #pragma unroll 8
    for (int d = 0; d < 64; d++) {
        float qv[4], kvr[4];
        #pragma unroll
        for (int i = 0; i < 4; i++) qv[i] = qs[r0 + i][d];
        *reinterpret_cast<float4*>(kvr) = *reinterpret_cast<float4*>(&kvs[d][e0]);
        float ksd = kss[d];
        #pragma unroll
        for (int i = 0; i < 4; i++) {
            nacc[i] += qv[i] * ksd;
            #pragma unroll
            for (int j = 0; j < 4; j++)
                acc[i][j] += qv[i] * kvr[j];
        }
    }

    #pragma unroll
    for (int i = 0; i < 4; i++) {
        float inv = 1.f / (nacc[i] + 1e-6f);
        uint32_t lo = h2u(__floats2half2_rn(acc[i][0] * inv, acc[i][1] * inv));
        uint32_t hi = h2u(__floats2half2_rn(acc[i][2] * inv, acc[i][3] * inv));
        int n = nb * 64 + r0 + i;
        *reinterpret_cast<uint2*>(
            &g_attnh[((size_t)b * N_ + n) * C_ + h * 64 + e0]) = make_uint2(lo, hi);
    }
}

// ============================================================
extern "C" void kernel_launch(void* const* d_in, const int* in_sizes, int n_in,
                              void* d_out, int out_size)
{
    const float* x     = (const float*)d_in[0];
    const float* W_qkv = (const float*)d_in[1];
    const float* W_out = (const float*)d_in[2];
    const float* b_out = (const float*)d_in[3];
    float* out = (float*)d_out;

    float *p_qkv;
    __half *p_xh, *p_attnh;
    uint32_t *p_wqkvP, *p_woutP;
    cudaGetSymbolAddress((void**)&p_qkv,   g_qkv);
    cudaGetSymbolAddress((void**)&p_xh,    g_xh);
    cudaGetSymbolAddress((void**)&p_attnh, g_attnh);
    cudaGetSymbolAddress((void**)&p_wqkvP, g_wqkvP);
    cudaGetSymbolAddress((void**)&p_woutP, g_woutP);

    cudaFuncSetAttribute(hgemm<1>, cudaFuncAttributeMaxDynamicSharedMemorySize, GEMM_SMEM);
    cudaFuncSetAttribute(hgemm<2>, cudaFuncAttributeMaxDynamicSharedMemorySize, GEMM_SMEM);

    // 0) convert inputs to fp16 (x elementwise; weights k-pair packed)
    conv_half_kernel<<<(M1 * C_ / 4 + 255) / 256, 256>>>(x, p_xh, M1 * C_ / 4);
    conv_pack_kernel<<<((C_ / 2) * N1 + 255) / 256, 256>>>(W_qkv, p_wqkvP, C_, N1);
    conv_pack_kernel<<<((C_ / 2) * C_ + 255) / 256, 256>>>(W_out, p_woutP, C_, C_);

    // 1) qkv = x @ W_qkv (fp16 tensor cores, fp32 accum), elu+1 fused
    hgemm<1><<<dim3(N1 / 128, M1 / 128), 128, GEMM_SMEM>>>(p_xh, p_wqkvP, p_qkv, M1, N1, C_, nullptr);
    // 2) kv / ksum split-K partials + reduce (fp32 exact)
    kv_partial_kernel<<<dim3(64, SPLITS), 256>>>(p_qkv);
    kv_reduce_kernel<<<64, 256>>>();
    // 3) numerator / normalizer / divide -> (B,N,C) half
    q_apply_kernel<<<dim3(64, 64), 256>>>(p_qkv);
    // 4) out = attn @ W_out + b_out (fp16 tensor cores, fp32 accum)
    hgemm<2><<<dim3(C_ / 128, M1 / 128), 128, GEMM_SMEM>>>(p_attnh, p_woutP, out, M1, C_, C_, b_out);
}

// round 15
// speedup vs baseline: 2.0128x; 1.0218x over previous
#include <cuda_runtime.h>
#include <cuda_fp16.h>
#include <cstdint>

#define B_ 4
#define N_ 4096
#define C_ 1024
#define H_ 16
#define D_ 64
#define M1 (B_*N_)      // 16384 rows
#define N1 (3*C_)       // 3072 qkv cols
#define SPLITS 16
#define CHUNK (N_/SPLITS) // 256 rows per split

// ---- scratch (no allocs allowed; __device__ globals) ----
__device__ __half g_qkvh[(size_t)M1 * N1];           // 100 MB qkv as half
__device__ __half g_xh  [(size_t)M1 * C_];           //  32 MB x as half
__device__ __half g_attnh[(size_t)M1 * C_];          //  32 MB attn as half
__device__ uint32_t g_wqkvP[(size_t)(C_/2) * N1];    //   6 MB W_qkv k-pair-packed half2
__device__ uint32_t g_woutP[(size_t)(C_/2) * C_];    //   2 MB W_out  k-pair-packed half2
__device__ float g_kvp [64 * SPLITS * 64 * 64];
__device__ float g_ksump[64 * SPLITS * 64];
__device__ float g_kv  [64 * 64 * 64];
__device__ float g_ksum[64 * 64];

// ============================================================
// helpers
// ============================================================
__device__ __forceinline__ uint32_t h2u(__half2 h) {
    return *reinterpret_cast<uint32_t*>(&h);
}

__device__ __forceinline__ void u4_to_f8(uint4 u, float* f) {
    __half2* hp = reinterpret_cast<__half2*>(&u);
    #pragma unroll
    for (int i = 0; i < 4; i++) {
        float2 t = __half22float2(hp[i]);
        f[2*i] = t.x; f[2*i+1] = t.y;
    }
}

__device__ __forceinline__ void mma_f16(float* c, const uint32_t* a, const uint32_t* b) {
    asm volatile(
        "mma.sync.aligned.m16n8k16.row.col.f32.f16.f16.f32 "
        "{%0,%1,%2,%3}, {%4,%5,%6,%7}, {%8,%9}, {%0,%1,%2,%3};"
        : "+f"(c[0]), "+f"(c[1]), "+f"(c[2]), "+f"(c[3])
        : "r"(a[0]), "r"(a[1]), "r"(a[2]), "r"(a[3]), "r"(b[0]), "r"(b[1]));
}

__device__ __forceinline__ void cp16s(void* smem_dst, const void* gmem_src) {
    asm volatile("cp.async.cg.shared.global [%0], [%1], 16;"
        :: "r"((uint32_t)__cvta_generic_to_shared(smem_dst)), "l"(gmem_src));
}
#define CP_COMMIT() asm volatile("cp.async.commit_group;" ::)
#define CP_WAIT(n)  asm volatile("cp.async.wait_group %0;" :: "n"(n))

// ============================================================
// fp16 tensor-core GEMM: C[M,N] = A[M,K] @ B[K,N], A half
// row-major, B k-pair-packed half2 [K/2][N] (u32).
// MODE 1: elu(x)+1 on cols < 2048, output HALF (g_qkvh).
// MODE 2: += bias[col], output FLOAT (d_out).
// 128x128 CTA tile, BK=32, 4-stage cp.async pipeline,
// 128 threads (4 warps, 2x2), warp tile 64x64. fp32 accum.
// ============================================================
#define BKH 32
#define APITCH 40                       // halves per A row
#define BPITCH 136                      // u32 per B row
#define A_BYTES (128 * APITCH * 2)      // 10240
#define B_BYTES (16 * BPITCH * 4)       // 8704
#define STG_BYTES (A_BYTES + B_BYTES)   // 18944
#define NSTG 4
#define GEMM_SMEM (NSTG * STG_BYTES)    // 75776

template<int MODE>
__global__ __launch_bounds__(128, 2) void hgemm(
    const __half* __restrict__ A, const uint32_t* __restrict__ Bp,
    void* __restrict__ Cout, int M, int N, int K,
    const float* __restrict__ bias)
{
    extern __shared__ char smem[];

    const int tid  = threadIdx.x;
    const int lane = tid & 31;
    const int warp = tid >> 5;
    const int wr = warp >> 1;            // 0..1  (64-row slabs)
    const int wc = warp & 1;             // 0..1  (64-col slabs)
    const int bx = blockIdx.x, by = blockIdx.y;
    const int la3 = lane & 3;
    const int l4  = lane >> 2;

    const __half*   Ab = A  + (size_t)(by * 128) * K;
    const uint32_t* Bb = Bp + bx * 128;

    #define LOAD_STAGE(s, kk)                                                   \
        do {                                                                    \
            char* as_ = smem + (s) * STG_BYTES;                                 \
            char* bs_ = as_ + A_BYTES;                                          \
            _Pragma("unroll")                                                   \
            for (int i = 0; i < 4; i++) {                                       \
                int j = tid + 128 * i;                                          \
                int m = j >> 2, c8 = j & 3;                                     \
                cp16s(as_ + m * (APITCH * 2) + c8 * 16,                         \
                      Ab + (size_t)m * K + (kk) + c8 * 8);                      \
            }                                                                   \
            _Pragma("unroll")                                                   \
            for (int i = 0; i < 4; i++) {                                       \
                int j = tid + 128 * i;                                          \
                int kp = j >> 5, c4 = j & 31;                                   \
                cp16s(bs_ + kp * (BPITCH * 4) + c4 * 16,                        \
                      Bb + (size_t)((kk) / 2 + kp) * N + c4 * 4);               \
            }                                                                   \
            CP_COMMIT();                                                        \
        } while (0)

    const int nT = K / BKH;
    LOAD_STAGE(0, 0);
    LOAD_STAGE(1, BKH);
    LOAD_STAGE(2, 2 * BKH);

    float acc[4][8][4] = {};

    for (int t = 0; t < nT; t++) {
        if (t + 2 < nT) { CP_WAIT(2); }
        else if (t + 1 < nT) { CP_WAIT(1); }
        else { CP_WAIT(0); }
        __syncthreads();

        if (t + 3 < nT) {
            LOAD_STAGE((t + 3) % NSTG, (t + 3) * BKH);
        }

        const char* as_ = smem + (t % NSTG) * STG_BYTES;
        const char* bs_ = as_ + A_BYTES;

        #pragma unroll
        for (int ks = 0; ks < BKH; ks += 16) {
            const int ks2 = ks >> 1;
            uint32_t af[4][4], bf[8][2];
            #pragma unroll
            for (int mt = 0; mt < 4; mt++) {
                int rb = wr * 64 + mt * 16 + l4;
                const char* r0 = as_ + rb * (APITCH * 2);
                af[mt][0] = *reinterpret_cast<const uint32_t*>(r0 + (ks + la3 * 2) * 2);
                af[mt][1] = *reinterpret_cast<const uint32_t*>(r0 + 8 * (APITCH * 2) + (ks + la3 * 2) * 2);
                af[mt][2] = *reinterpret_cast<const uint32_t*>(r0 + (ks + 8 + la3 * 2) * 2);
                af[mt][3] = *reinterpret_cast<const uint32_t*>(r0 + 8 * (APITCH * 2) + (ks + 8 + la3 * 2) * 2);
            }
            #pragma unroll
            for (int nt = 0; nt < 8; nt++) {
                int nb = wc * 64 + nt * 8 + l4;
                bf[nt][0] = *reinterpret_cast<const uint32_t*>(bs_ + (ks2 + la3)     * (BPITCH * 4) + nb * 4);
                bf[nt][1] = *reinterpret_cast<const uint32_t*>(bs_ + (ks2 + 4 + la3) * (BPITCH * 4) + nb * 4);
            }
            #pragma unroll
            for (int mt = 0; mt < 4; mt++)
                #pragma unroll
                for (int nt = 0; nt < 8; nt++)
                    mma_f16(acc[mt][nt], af[mt], bf[nt]);
        }
        __syncthreads();
    }

    // epilogue
    #pragma unroll
    for (int mt = 0; mt < 4; mt++) {
        #pragma unroll
        for (int nt = 0; nt < 8; nt++) {
            int row = by * 128 + wr * 64 + mt * 16 + l4;
            int col = bx * 128 + wc * 64 + nt * 8 + la3 * 2;
            float v0 = acc[mt][nt][0], v1 = acc[mt][nt][1];
            float v2 = acc[mt][nt][2], v3 = acc[mt][nt][3];
            if (MODE == 1) {
                if (col < 2 * C_) {   // q,k columns: elu(x)+1
                    v0 = (v0 > 0.f) ? (v0 + 1.f) : __expf(v0);
                    v1 = (v1 > 0.f) ? (v1 + 1.f) : __expf(v1);
                    v2 = (v2 > 0.f) ? (v2 + 1.f) : __expf(v2);
                    v3 = (v3 > 0.f) ? (v3 + 1.f) : __expf(v3);
                }
                __half* Ch = (__half*)Cout;
                *reinterpret_cast<uint32_t*>(Ch + (size_t)row * N + col) =
                    h2u(__floats2half2_rn(v0, v1));
                *reinterpret_cast<uint32_t*>(Ch + (size_t)(row + 8) * N + col) =
                    h2u(__floats2half2_rn(v2, v3));
            } else {
                float b0 = bias[col], b1 = bias[col + 1];
                v0 += b0; v1 += b1; v2 += b0; v3 += b1;
                float* Cf = (float*)Cout;
                *reinterpret_cast<float2*>(Cf + (size_t)row * N + col)       = make_float2(v0, v1);
                *reinterpret_cast<float2*>(Cf + (size_t)(row + 8) * N + col) = make_float2(v2, v3);
            }
        }
    }
}

// ============================================================
// conversion kernels
// ============================================================
__global__ __launch_bounds__(256) void conv_half_kernel(
    const float* __restrict__ in, __half* __restrict__ out, int n4)
{
    int i = blockIdx.x * blockDim.x + threadIdx.x;
    if (i < n4) {
        float4 v = reinterpret_cast<const float4*>(in)[i];
        uint32_t lo = h2u(__floats2half2_rn(v.x, v.y));
        uint32_t hi = h2u(__floats2half2_rn(v.z, v.w));
        reinterpret_cast<uint2*>(out)[i] = make_uint2(lo, hi);
    }
}

__global__ __launch_bounds__(256) void conv_pack_kernel(
    const float* __restrict__ W, uint32_t* __restrict__ out, int K, int N)
{
    int i = blockIdx.x * blockDim.x + threadIdx.x;
    int total = (K / 2) * N;
    if (i < total) {
        int kp = i / N, n = i % N;
        float lo = W[(size_t)(2 * kp) * N + n];
        float hi = W[(size_t)(2 * kp + 1) * N + n];
        out[i] = h2u(__floats2half2_rn(lo, hi));
    }
}

// ============================================================
// Phase 2: per (b,h) split-K partials of kv[d][e] = sum_n k*v
// and ksum[d] = sum_n k. Half inputs, fp32 accumulate.
// Deterministic (no atomics).
// ============================================================
__global__ __launch_bounds__(256) void kv_partial_kernel(const __half* __restrict__ qkv)
{
    int bh = blockIdx.x;
    int b = bh >> 4, h = bh & 15;
    int n0 = blockIdx.y * CHUNK;
    int tid = threadIdx.x;
    int d0 = (tid >> 4) * 4, e0 = (tid & 15) * 4;

    __shared__ float ks[32][64];
    __shared__ float vs[32][64];

    float acc[4][4] = {};
    float ksacc[4] = {0.f, 0.f, 0.f, 0.f};

    const __half* base = qkv + (size_t)b * N_ * N1 + h * 64;

    // load map: 256 threads, each owns one 8-half chunk of k and of v
    const int lr = tid >> 3;           // 0..31 row
    const int lc = (tid & 7) * 8;      // 0..56 col

    for (int nt = 0; nt < CHUNK; nt += 32) {
        size_t off = (size_t)(n0 + nt + lr) * N1 + lc;
        uint4 ku = *reinterpret_cast<const uint4*>(base + 1024 + off);
        uint4 vu = *reinterpret_cast<const uint4*>(base + 2048 + off);
        u4_to_f8(ku, &ks[lr][lc]);
        u4_to_f8(vu, &vs[lr][lc]);
        __syncthreads();
        #pragma unroll 4
        for (int r = 0; r < 32; r++) {
            float kr[4], vr[4];
            *reinterpret_cast<float4*>(kr) = *reinterpret_cast<float4*>(&ks[r][d0]);
            *reinterpret_cast<float4*>(vr) = *reinterpret_cast<float4*>(&vs[r][e0]);
            #pragma unroll
            for (int i = 0; i < 4; i++)
                #pragma unroll
                for (int j = 0; j < 4; j++)
                    acc[i][j] += kr[i] * vr[j];
            if (e0 == 0) {
                #pragma unroll
                for (int i = 0; i < 4; i++) ksacc[i] += kr[i];
            }
        }
        __syncthreads();
    }

    float* kvp = g_kvp + (size_t)(bh * SPLITS + blockIdx.y) * 4096;
    #pragma unroll
    for (int i = 0; i < 4; i++)
        #pragma unroll
        for (int j = 0; j < 4; j++)
            kvp[(d0 + i) * 64 + e0 + j] = acc[i][j];
    if (e0 == 0) {
        float* ksp = g_ksump + (size_t)(bh * SPLITS + blockIdx.y) * 64;
        #pragma unroll
        for (int i = 0; i < 4; i++) ksp[d0 + i] = ksacc[i];
    }
}

__global__ __launch_bounds__(256) void kv_reduce_kernel()
{
    int bh = blockIdx.x; int tid = threadIdx.x;
    for (int idx = tid; idx < 4096; idx += 256) {
        float s = 0.f;
        #pragma unroll
        for (int p = 0; p < SPLITS; p++)
            s += g_kvp[(size_t)(bh * SPLITS + p) * 4096 + idx];
        g_kv[(size_t)bh * 4096 + idx] = s;
    }
    if (tid < 64) {
        float s = 0.f;
        #pragma unroll
        for (int p = 0; p < SPLITS; p++)
            s += g_ksump[(size_t)(bh * SPLITS + p) * 64 + tid];
        g_ksum[bh * 64 + tid] = s;
    }
}

// ============================================================
// Phase 3: out[n,e] = (q[n,:] @ kv[:,e]) / (q[n,:]·ksum + 1e-6)
// Half q input, fp32 math; stores half (feeds fp16 GEMM2 A).
// ============================================================
__global__ __launch_bounds__(256) void q_apply_kernel(const __half* __restrict__ qkv)
{
    int bh = blockIdx.x; int b = bh >> 4, h = bh & 15;
    int nb = blockIdx.y;
    int tid = threadIdx.x;

    __shared__ float kvs[64][68];   // kvs[d][e]
    __shared__ float qs [64][68];   // qs[r][d]
    __shared__ float kss[64];

    {
        const float* src = g_kv + (size_t)bh * 4096;
        for (int l = tid; l < 1024; l += 256) {
            int d = l >> 4; int e = (l & 15) * 4;
            *reinterpret_cast<float4*>(&kvs[d][e]) =
                *reinterpret_cast<const float4*>(src + d * 64 + e);
        }
    }
    if (tid < 64) kss[tid] = g_ksum[bh * 64 + tid];

    const __half* qbase = qkv + ((size_t)b * N_ + nb * 64) * N1 + h * 64;
    for (int l = tid; l < 512; l += 256) {        // 64 rows x 8 chunks of 8 halves
        int r = l >> 3; int c = (l & 7) * 8;
        uint4 qu = *reinterpret_cast<const uint4*>(qbase + (size_t)r * N1 + c);
        u4_to_f8(qu, &qs[r][c]);
    }
    __syncthreads();

    const int r0 = (tid >> 4) * 4;
    const int e0 = (tid & 15) * 4;

    float acc[4][4] = {};
    float nacc[4] = {0.f, 0.f, 0.f, 0.f};

    #pragma unroll 8
    for (int d = 0; d < 64; d++) {
        float qv[4], kvr[4];
        #pragma unroll
        for (int i = 0; i < 4; i++) qv[i] = qs[r0 + i][d];
        *reinterpret_cast<float4*>(kvr) = *reinterpret_cast<float4*>(&kvs[d][e0]);
        float ksd = kss[d];
        #pragma unroll
        for (int i = 0; i < 4; i++) {
            nacc[i] += qv[i] * ksd;
            #pragma unroll
            for (int j = 0; j < 4; j++)
                acc[i][j] += qv[i] * kvr[j];
        }
    }

    #pragma unroll
    for (int i = 0; i < 4; i++) {
        float inv = 1.f / (nacc[i] + 1e-6f);
        uint32_t lo = h2u(__floats2half2_rn(acc[i][0] * inv, acc[i][1] * inv));
        uint32_t hi = h2u(__floats2half2_rn(acc[i][2] * inv, acc[i][3] * inv));
        int n = nb * 64 + r0 + i;
        *reinterpret_cast<uint2*>(
            &g_attnh[((size_t)b * N_ + n) * C_ + h * 64 + e0]) = make_uint2(lo, hi);
    }
}

// ============================================================
extern "C" void kernel_launch(void* const* d_in, const int* in_sizes, int n_in,
                              void* d_out, int out_size)
{
    const float* x     = (const float*)d_in[0];
    const float* W_qkv = (const float*)d_in[1];
    const float* W_out = (const float*)d_in[2];
    const float* b_out = (const float*)d_in[3];

    __half *p_qkvh, *p_xh, *p_attnh;
    uint32_t *p_wqkvP, *p_woutP;
    cudaGetSymbolAddress((void**)&p_qkvh,  g_qkvh);
    cudaGetSymbolAddress((void**)&p_xh,    g_xh);
    cudaGetSymbolAddress((void**)&p_attnh, g_attnh);
    cudaGetSymbolAddress((void**)&p_wqkvP, g_wqkvP);
    cudaGetSymbolAddress((void**)&p_woutP, g_woutP);

    cudaFuncSetAttribute(hgemm<1>, cudaFuncAttributeMaxDynamicSharedMemorySize, GEMM_SMEM);
    cudaFuncSetAttribute(hgemm<2>, cudaFuncAttributeMaxDynamicSharedMemorySize, GEMM_SMEM);

    // 0) convert inputs to fp16 (x elementwise; weights k-pair packed)
    conv_half_kernel<<<(M1 * C_ / 4 + 255) / 256, 256>>>(x, p_xh, M1 * C_ / 4);
    conv_pack_kernel<<<((C_ / 2) * N1 + 255) / 256, 256>>>(W_qkv, p_wqkvP, C_, N1);
    conv_pack_kernel<<<((C_ / 2) * C_ + 255) / 256, 256>>>(W_out, p_woutP, C_, C_);

    // 1) qkv = x @ W_qkv (fp16 tensor cores, fp32 accum), elu+1 fused, half out
    hgemm<1><<<dim3(N1 / 128, M1 / 128), 128, GEMM_SMEM>>>(p_xh, p_wqkvP, p_qkvh, M1, N1, C_, nullptr);
    // 2) kv / ksum split-K partials + reduce (half in, fp32 accum)
    kv_partial_kernel<<<dim3(64, SPLITS), 256>>>(p_qkvh);
    kv_reduce_kernel<<<64, 256>>>();
    // 3) numerator / normalizer / divide -> (B,N,C) half
    q_apply_kernel<<<dim3(64, 64), 256>>>(p_qkvh);
    // 4) out = attn @ W_out + b_out (fp16 tensor cores, fp32 accum), float out
    hgemm<2><<<dim3(C_ / 128, M1 / 128), 128, GEMM_SMEM>>>(p_attnh, p_woutP, d_out, M1, C_, C_, b_out);
}